// round 1
// baseline (speedup 1.0000x reference)
#include <cuda_runtime.h>

#define Bn 32
#define Nn 577
#define Cn 768
#define Hn 12
#define Dn 64
#define Mn (Bn*Nn)          // 18464 rows
#define QKV_N (3*Cn)        // 2304

// Scratch (allocation-free rule: __device__ globals)
__device__ __align__(16) float g_q[Bn*Hn*Nn*Dn];
__device__ __align__(16) float g_k[Bn*Hn*Nn*Dn];
__device__ __align__(16) float g_v[Bn*Hn*Nn*Dn];
__device__ __align__(16) float g_ao[Mn*Cn];

// ---------------------------------------------------------------------------
// Kernel 1: QKV = X @ Wqkv^T  (NT SGEMM 128x128x16), epilogue: RoPE + scale(q)
//           + scatter into g_q/g_k/g_v laid out [B,H,N,D].
// ---------------------------------------------------------------------------
__global__ __launch_bounds__(256) void qkv_kernel(
    const float* __restrict__ X, const float* __restrict__ W,
    const float* __restrict__ cosb, const float* __restrict__ sinb)
{
    __shared__ __align__(16) float As[16][132];
    __shared__ __align__(16) float Bs[16][132];
    const int K  = Cn;
    const int m0 = blockIdx.y * 128;
    const int n0 = blockIdx.x * 128;
    const int tid  = threadIdx.x;
    const int tr   = tid >> 4;          // 0..15
    const int tc   = tid & 15;          // 0..15
    const int lrow = tid >> 2;          // 0..63
    const int lcol = (tid & 3) << 2;    // 0,4,8,12

    float acc[8][8];
#pragma unroll
    for (int i = 0; i < 8; i++)
#pragma unroll
        for (int j = 0; j < 8; j++) acc[i][j] = 0.f;

    for (int kt = 0; kt < K; kt += 16) {
#pragma unroll
        for (int p = 0; p < 2; p++) {
            const int mr = lrow + p*64;
            const int r  = m0 + mr;
            float4 a = (r < Mn) ? *(const float4*)(X + (size_t)r*K + kt + lcol)
                                : make_float4(0.f,0.f,0.f,0.f);
            As[lcol+0][mr] = a.x; As[lcol+1][mr] = a.y;
            As[lcol+2][mr] = a.z; As[lcol+3][mr] = a.w;
            const int jr = n0 + mr;
            float4 b = *(const float4*)(W + (size_t)jr*K + kt + lcol);
            Bs[lcol+0][mr] = b.x; Bs[lcol+1][mr] = b.y;
            Bs[lcol+2][mr] = b.z; Bs[lcol+3][mr] = b.w;
        }
        __syncthreads();
#pragma unroll
        for (int k = 0; k < 16; k++) {
            float4 a0 = *(const float4*)&As[k][tr*8];
            float4 a1 = *(const float4*)&As[k][tr*8+4];
            float4 b0 = *(const float4*)&Bs[k][tc*8];
            float4 b1 = *(const float4*)&Bs[k][tc*8+4];
            float rm[8] = {a0.x,a0.y,a0.z,a0.w,a1.x,a1.y,a1.z,a1.w};
            float rn[8] = {b0.x,b0.y,b0.z,b0.w,b1.x,b1.y,b1.z,b1.w};
#pragma unroll
            for (int i = 0; i < 8; i++)
#pragma unroll
                for (int j = 0; j < 8; j++) acc[i][j] += rm[i]*rn[j];
        }
        __syncthreads();
    }

    // Epilogue: RoPE (pairs of adjacent even/odd columns stay within a thread),
    // scale q by D^-0.5, scatter to [B,H,N,D].
#pragma unroll
    for (int i = 0; i < 8; i++) {
        const int r = m0 + tr*8 + i;
        if (r < Mn) {
            const int bb = r / Nn;
            const int n  = r - bb*Nn;
#pragma unroll
            for (int j = 0; j < 8; j += 2) {
                const int c   = n0 + tc*8 + j;
                const int sec = c / Cn;          // 0=q 1=k 2=v
                const int rem = c - sec*Cn;
                const int h   = rem >> 6;
                const int d   = rem & 63;        // even
                float v1 = acc[i][j], v2 = acc[i][j+1];
                if (sec < 2 && n > 0) {
                    const float cc = cosb[(n-1)*(Dn/2) + (d>>1)];
                    const float ss = sinb[(n-1)*(Dn/2) + (d>>1)];
                    const float r1 = v1*cc - v2*ss;
                    const float r2 = v1*ss + v2*cc;
                    v1 = r1; v2 = r2;
                }
                if (sec == 0) { v1 *= 0.125f; v2 *= 0.125f; }   // HEAD_DIM^-0.5
                float* dst = (sec == 0) ? g_q : ((sec == 1) ? g_k : g_v);
                const int idx = ((bb*Hn + h)*Nn + n)*Dn + d;
                dst[idx]   = v1;
                dst[idx+1] = v2;
            }
        }
    }
}

// ---------------------------------------------------------------------------
// Kernel 2: flash attention. One block = (b,h) x 64-row q-tile.
// smem: Qs[64][64] row-major, KT[64][64] = K transposed [d][krow] (reused as
// P[qrow][krow] after S), Vs[64][64] row-major. Exactly 48 KB.
// ---------------------------------------------------------------------------
__global__ __launch_bounds__(256) void attn_kernel()
{
    __shared__ __align__(16) float Qs[64*64];
    __shared__ __align__(16) float KT[64*64];   // K^T during S, then P
    __shared__ __align__(16) float Vs[64*64];

    const int qt  = blockIdx.x;          // 0..9
    const int bh  = blockIdx.y;          // 0..383  (= b*H + h)
    const int tid = threadIdx.x;
    const int ty  = tid >> 4;            // 0..15 -> 4 q rows each
    const int tx  = tid & 15;            // 0..15 -> 4 cols each
    const int lr  = tid >> 2;            // 0..63 load row
    const int lc  = (tid & 3) << 4;      // 0,16,32,48 load col base

    const float* Qg = g_q + (size_t)bh*Nn*Dn;
    const float* Kg = g_k + (size_t)bh*Nn*Dn;
    const float* Vg = g_v + (size_t)bh*Nn*Dn;

    // Load Q tile (zero-padded)
    {
        const int r = qt*64 + lr;
#pragma unroll
        for (int q = 0; q < 16; q += 4) {
            float4 v = (r < Nn) ? *(const float4*)(Qg + (size_t)r*Dn + lc + q)
                                : make_float4(0.f,0.f,0.f,0.f);
            Qs[lr*64 + lc+q+0] = v.x; Qs[lr*64 + lc+q+1] = v.y;
            Qs[lr*64 + lc+q+2] = v.z; Qs[lr*64 + lc+q+3] = v.w;
        }
    }

    float m_i[4], l_i[4], O[4][4];
#pragma unroll
    for (int i = 0; i < 4; i++) {
        m_i[i] = -1e30f; l_i[i] = 0.f;
#pragma unroll
        for (int j = 0; j < 4; j++) O[i][j] = 0.f;
    }

    const int NT = (Nn + 63) / 64;   // 10
    for (int t = 0; t < NT; t++) {
        __syncthreads();   // protect KT/Vs reuse (and Qs store on t=0)
        {
            const int r = t*64 + lr;
            const bool ok = (r < Nn);
#pragma unroll
            for (int q = 0; q < 16; q += 4) {
                float4 kv = ok ? *(const float4*)(Kg + (size_t)r*Dn + lc + q)
                               : make_float4(0.f,0.f,0.f,0.f);
                KT[(lc+q+0)*64 + lr] = kv.x;
                KT[(lc+q+1)*64 + lr] = kv.y;
                KT[(lc+q+2)*64 + lr] = kv.z;
                KT[(lc+q+3)*64 + lr] = kv.w;
                float4 vv = ok ? *(const float4*)(Vg + (size_t)r*Dn + lc + q)
                               : make_float4(0.f,0.f,0.f,0.f);
                Vs[lr*64 + lc+q+0] = vv.x; Vs[lr*64 + lc+q+1] = vv.y;
                Vs[lr*64 + lc+q+2] = vv.z; Vs[lr*64 + lc+q+3] = vv.w;
            }
        }
        __syncthreads();

        // S = (Q*scale) @ K^T   (scale already folded into Q)
        float s[4][4];
#pragma unroll
        for (int i = 0; i < 4; i++)
#pragma unroll
            for (int j = 0; j < 4; j++) s[i][j] = 0.f;

#pragma unroll 4
        for (int d4 = 0; d4 < 64; d4 += 4) {
            float4 q4[4];
#pragma unroll
            for (int i = 0; i < 4; i++)
                q4[i] = *(const float4*)&Qs[(ty*4+i)*64 + d4];
#pragma unroll
            for (int u = 0; u < 4; u++) {
                float4 k4 = *(const float4*)&KT[(d4+u)*64 + tx*4];
                const float kf[4] = {k4.x,k4.y,k4.z,k4.w};
#pragma unroll
                for (int i = 0; i < 4; i++) {
                    const float qf = (u==0)?q4[i].x:(u==1)?q4[i].y:(u==2)?q4[i].z:q4[i].w;
#pragma unroll
                    for (int j = 0; j < 4; j++) s[i][j] += qf * kf[j];
                }
            }
        }

        // mask out-of-range k columns
        const int kb = t*64 + tx*4;
#pragma unroll
        for (int j = 0; j < 4; j++)
            if (kb + j >= Nn) {
#pragma unroll
                for (int i = 0; i < 4; i++) s[i][j] = -1e30f;
            }

        __syncthreads();   // all KT reads done before P overwrites it

        // online softmax per row (row group = 16 lanes sharing ty)
#pragma unroll
        for (int i = 0; i < 4; i++) {
            float mx = fmaxf(fmaxf(s[i][0],s[i][1]), fmaxf(s[i][2],s[i][3]));
#pragma unroll
            for (int off = 8; off > 0; off >>= 1)
                mx = fmaxf(mx, __shfl_xor_sync(0xffffffffu, mx, off, 16));
            const float mnew  = fmaxf(m_i[i], mx);
            const float alpha = __expf(m_i[i] - mnew);
            const float p0 = __expf(s[i][0]-mnew), p1 = __expf(s[i][1]-mnew);
            const float p2 = __expf(s[i][2]-mnew), p3 = __expf(s[i][3]-mnew);
            float rs = p0+p1+p2+p3;
#pragma unroll
            for (int off = 8; off > 0; off >>= 1)
                rs += __shfl_xor_sync(0xffffffffu, rs, off, 16);
            l_i[i] = l_i[i]*alpha + rs;
            m_i[i] = mnew;
#pragma unroll
            for (int j = 0; j < 4; j++) O[i][j] *= alpha;
            *(float4*)&KT[(ty*4+i)*64 + tx*4] = make_float4(p0,p1,p2,p3);  // P
        }
        __syncthreads();

        // O += P @ V
#pragma unroll 4
        for (int k4 = 0; k4 < 64; k4 += 4) {
            float4 p4[4];
#pragma unroll
            for (int i = 0; i < 4; i++)
                p4[i] = *(const float4*)&KT[(ty*4+i)*64 + k4];
#pragma unroll
            for (int u = 0; u < 4; u++) {
                float4 v4 = *(const float4*)&Vs[(k4+u)*64 + tx*4];
                const float vf[4] = {v4.x,v4.y,v4.z,v4.w};
#pragma unroll
                for (int i = 0; i < 4; i++) {
                    const float pf = (u==0)?p4[i].x:(u==1)?p4[i].y:(u==2)?p4[i].z:p4[i].w;
#pragma unroll
                    for (int j = 0; j < 4; j++) O[i][j] += pf * vf[j];
                }
            }
        }
    }

    // write [B,N,H*D]
    const int bb = bh / Hn;
    const int h  = bh - bb*Hn;
#pragma unroll
    for (int i = 0; i < 4; i++) {
        const int qr = qt*64 + ty*4 + i;
        if (qr < Nn) {
            const float inv = 1.0f / l_i[i];
            float4 o4 = make_float4(O[i][0]*inv, O[i][1]*inv, O[i][2]*inv, O[i][3]*inv);
            *(float4*)&g_ao[((size_t)bb*Nn + qr)*Cn + h*Dn + tx*4] = o4;
        }
    }
}

// ---------------------------------------------------------------------------
// Kernel 3: out = g_ao @ Wproj^T + bias
// ---------------------------------------------------------------------------
__global__ __launch_bounds__(256) void proj_kernel(
    const float* __restrict__ W, const float* __restrict__ bias,
    float* __restrict__ out)
{
    __shared__ __align__(16) float As[16][132];
    __shared__ __align__(16) float Bs[16][132];
    const int K  = Cn;
    const int m0 = blockIdx.y * 128;
    const int n0 = blockIdx.x * 128;
    const int tid  = threadIdx.x;
    const int tr   = tid >> 4;
    const int tc   = tid & 15;
    const int lrow = tid >> 2;
    const int lcol = (tid & 3) << 2;

    float acc[8][8];
#pragma unroll
    for (int i = 0; i < 8; i++)
#pragma unroll
        for (int j = 0; j < 8; j++) acc[i][j] = 0.f;

    for (int kt = 0; kt < K; kt += 16) {
#pragma unroll
        for (int p = 0; p < 2; p++) {
            const int mr = lrow + p*64;
            const int r  = m0 + mr;
            float4 a = (r < Mn) ? *(const float4*)(g_ao + (size_t)r*K + kt + lcol)
                                : make_float4(0.f,0.f,0.f,0.f);
            As[lcol+0][mr] = a.x; As[lcol+1][mr] = a.y;
            As[lcol+2][mr] = a.z; As[lcol+3][mr] = a.w;
            const int jr = n0 + mr;
            float4 b = *(const float4*)(W + (size_t)jr*K + kt + lcol);
            Bs[lcol+0][mr] = b.x; Bs[lcol+1][mr] = b.y;
            Bs[lcol+2][mr] = b.z; Bs[lcol+3][mr] = b.w;
        }
        __syncthreads();
#pragma unroll
        for (int k = 0; k < 16; k++) {
            float4 a0 = *(const float4*)&As[k][tr*8];
            float4 a1 = *(const float4*)&As[k][tr*8+4];
            float4 b0 = *(const float4*)&Bs[k][tc*8];
            float4 b1 = *(const float4*)&Bs[k][tc*8+4];
            float rm[8] = {a0.x,a0.y,a0.z,a0.w,a1.x,a1.y,a1.z,a1.w};
            float rn[8] = {b0.x,b0.y,b0.z,b0.w,b1.x,b1.y,b1.z,b1.w};
#pragma unroll
            for (int i = 0; i < 8; i++)
#pragma unroll
                for (int j = 0; j < 8; j++) acc[i][j] += rm[i]*rn[j];
        }
        __syncthreads();
    }

#pragma unroll
    for (int i = 0; i < 8; i++) {
        const int r = m0 + tr*8 + i;
        if (r < Mn) {
#pragma unroll
            for (int j = 0; j < 8; j++) {
                const int c = n0 + tc*8 + j;
                out[(size_t)r*Cn + c] = acc[i][j] + bias[c];
            }
        }
    }
}

// ---------------------------------------------------------------------------
extern "C" void kernel_launch(void* const* d_in, const int* in_sizes, int n_in,
                              void* d_out, int out_size)
{
    (void)in_sizes; (void)n_in; (void)out_size;
    const float* x      = (const float*)d_in[0];
    const float* w_qkv  = (const float*)d_in[1];
    const float* w_proj = (const float*)d_in[2];
    const float* b_proj = (const float*)d_in[3];
    const float* cosb   = (const float*)d_in[4];
    const float* sinb   = (const float*)d_in[5];
    float* out = (float*)d_out;

    dim3 blk(256);
    qkv_kernel<<<dim3(QKV_N/128, (Mn+127)/128), blk>>>(x, w_qkv, cosb, sinb);
    attn_kernel<<<dim3((Nn+63)/64, Bn*Hn), blk>>>();
    proj_kernel<<<dim3(Cn/128, (Mn+127)/128), blk>>>(w_proj, b_proj, out);
}

// round 3
// speedup vs baseline: 1.4047x; 1.4047x over previous
#include <cuda_runtime.h>
#include <cuda_bf16.h>
#include <cstdint>

#define Bn 32
#define Nn 577
#define Cn 768
#define Hn 12
#define Dn 64
#define Mn (Bn*Nn)          // 18464
#define QKV_N (3*Cn)        // 2304

// Scratch (__device__ globals: allocation-free rule)
__device__ __align__(16) float g_qkv[(size_t)Mn*QKV_N];   // [B*N, 3C]
__device__ __align__(16) float g_ao[(size_t)Mn*Cn];

// ---------------------------------------------------------------------------
// helpers
// ---------------------------------------------------------------------------
__device__ __forceinline__ uint32_t smem_u32(const void* p){
    uint32_t a;
    asm("{ .reg .u64 t; cvta.to.shared.u64 t, %1; cvt.u32.u64 %0, t; }"
        : "=r"(a) : "l"(p));
    return a;
}
__device__ __forceinline__ void ldsm4(uint32_t (&r)[4], uint32_t a){
    asm volatile("ldmatrix.sync.aligned.m8n8.x4.shared.b16 {%0,%1,%2,%3}, [%4];"
        : "=r"(r[0]),"=r"(r[1]),"=r"(r[2]),"=r"(r[3]) : "r"(a));
}
__device__ __forceinline__ void mma16816(float* c, const uint32_t* a,
                                         uint32_t b0, uint32_t b1){
    asm volatile("mma.sync.aligned.m16n8k16.row.col.f32.bf16.bf16.f32 "
        "{%0,%1,%2,%3}, {%4,%5,%6,%7}, {%8,%9}, {%0,%1,%2,%3};"
        : "+f"(c[0]),"+f"(c[1]),"+f"(c[2]),"+f"(c[3])
        : "r"(a[0]),"r"(a[1]),"r"(a[2]),"r"(a[3]), "r"(b0),"r"(b1));
}
// 8 fp32 -> 4 b32 hi-bf16 pairs + 4 b32 lo-bf16 pairs (hi + lo ≈ fp32)
__device__ __forceinline__ void cvt8_split(float4 a, float4 b, uint32_t* h, uint32_t* l){
    float f[8] = {a.x,a.y,a.z,a.w,b.x,b.y,b.z,b.w};
    float hf[8];
#pragma unroll
    for (int i=0;i<8;i++) hf[i] = __bfloat162float(__float2bfloat16(f[i]));
#pragma unroll
    for (int i=0;i<4;i++){
        __nv_bfloat162 hh = __floats2bfloat162_rn(f[2*i],          f[2*i+1]);
        __nv_bfloat162 ll = __floats2bfloat162_rn(f[2*i]-hf[2*i],  f[2*i+1]-hf[2*i+1]);
        h[i] = *reinterpret_cast<uint32_t*>(&hh);
        l[i] = *reinterpret_cast<uint32_t*>(&ll);
    }
}

// ---------------------------------------------------------------------------
// HMMA bf16x3 GEMM: D[128x128] = A[M,768] @ B[N,768]^T (fp32 accum)
// Smem tiles: 128 rows x 32 bf16, 80B pitch (64B data + 16B pad -> LDSM
// bank-group (5*row+q)&7 is a permutation over 8 consecutive rows).
// Stage: Ah | Al | Bh | Bl @ 10240B each = 40960B; 2 stages.
// EPI==0: qkv epilogue (RoPE + q-scale -> g_qkv). EPI==1: +bias -> Out.
// ---------------------------------------------------------------------------
#define KT 32
#define NKT (Cn/KT)          // 24
#define TILE_B 10240
#define STAGE_B 40960
#define SMEM_DYN (2*STAGE_B)

template<int EPI>
__global__ __launch_bounds__(256) void gemm_tc(
    const float* __restrict__ Ain, const float* __restrict__ Bw,
    const float* __restrict__ cosb, const float* __restrict__ sinb,
    const float* __restrict__ bias, float* __restrict__ Out)
{
    extern __shared__ char sm[];
    const float* A = (EPI==1) ? (const float*)g_ao : Ain;

    const int tid  = threadIdx.x;
    const int wid  = tid >> 5;
    const int lane = tid & 31;
    const int m0 = blockIdx.y * 128;
    const int n0 = blockIdx.x * 128;

    // producer mapping: 16 fp32 per thread per tile (A and B)
    const int row  = tid >> 1;          // 0..127
    const int half = tid & 1;           // 0..1
    const bool mok = (m0 + row) < Mn;
    const float* pa = A  + (size_t)(m0+row)*Cn + half*16;
    const float* pb = Bw + (size_t)(n0+row)*Cn + half*16;
    const uint32_t sts_off = (uint32_t)row*80 + (uint32_t)half*32;

    const uint32_t smb = smem_u32(sm);

    // consumer (warp) mapping: warp tile 32(m) x 64(n)
    const int wm = wid & 3;
    const int wn = wid >> 2;
    const uint32_t a_lane = (uint32_t)((wm*32 + (lane&15))*80 + (lane>>4)*16);
    const uint32_t b_lane = (uint32_t)((wn*64 + (lane&7) + ((lane>>4)<<3))*80
                                       + ((lane>>3)&1)*16);

    float acc[2][8][4];
#pragma unroll
    for (int im=0;im<2;im++)
#pragma unroll
        for (int j=0;j<8;j++)
#pragma unroll
            for (int q=0;q<4;q++) acc[im][j][q] = 0.f;

    float4 a4[4], b4[4];

#define LDG_STAGE(s_) do{ \
    const float* qa = pa + (s_)*KT; const float* qb = pb + (s_)*KT; \
    if (mok){ a4[0]=*(const float4*)qa;     a4[1]=*(const float4*)(qa+4); \
              a4[2]=*(const float4*)(qa+8); a4[3]=*(const float4*)(qa+12);} \
    else { a4[0]=a4[1]=a4[2]=a4[3]=make_float4(0.f,0.f,0.f,0.f); } \
    b4[0]=*(const float4*)qb;     b4[1]=*(const float4*)(qb+4); \
    b4[2]=*(const float4*)(qb+8); b4[3]=*(const float4*)(qb+12); }while(0)

#define STS_STAGE(s_) do{ \
    char* sp = sm + (size_t)((s_)&1)*STAGE_B; \
    uint32_t h[4], l[4]; \
    cvt8_split(a4[0],a4[1],h,l); \
    *(uint4*)(sp + sts_off)              = make_uint4(h[0],h[1],h[2],h[3]); \
    *(uint4*)(sp + TILE_B + sts_off)     = make_uint4(l[0],l[1],l[2],l[3]); \
    cvt8_split(a4[2],a4[3],h,l); \
    *(uint4*)(sp + sts_off + 16)         = make_uint4(h[0],h[1],h[2],h[3]); \
    *(uint4*)(sp + TILE_B + sts_off + 16)= make_uint4(l[0],l[1],l[2],l[3]); \
    cvt8_split(b4[0],b4[1],h,l); \
    *(uint4*)(sp + 2*TILE_B + sts_off)   = make_uint4(h[0],h[1],h[2],h[3]); \
    *(uint4*)(sp + 3*TILE_B + sts_off)   = make_uint4(l[0],l[1],l[2],l[3]); \
    cvt8_split(b4[2],b4[3],h,l); \
    *(uint4*)(sp + 2*TILE_B + sts_off+16)= make_uint4(h[0],h[1],h[2],h[3]); \
    *(uint4*)(sp + 3*TILE_B + sts_off+16)= make_uint4(l[0],l[1],l[2],l[3]); }while(0)

    LDG_STAGE(0);
    STS_STAGE(0);
    __syncthreads();

    for (int s = 0; s < NKT; s++){
        if (s+1 < NKT) LDG_STAGE(s+1);

        const uint32_t sb = smb + (uint32_t)(s&1)*STAGE_B;
#pragma unroll
        for (int kk = 0; kk < 2; kk++){
            uint32_t ah[2][4], al[2][4];
            ldsm4(ah[0], sb + a_lane + kk*32);
            ldsm4(ah[1], sb + a_lane + 16*80 + kk*32);
            ldsm4(al[0], sb + TILE_B + a_lane + kk*32);
            ldsm4(al[1], sb + TILE_B + a_lane + 16*80 + kk*32);
            uint32_t bh[4][4], bl[4][4];
#pragma unroll
            for (int t2 = 0; t2 < 4; t2++){
                ldsm4(bh[t2], sb + 2*TILE_B + b_lane + t2*16*80 + kk*32);
                ldsm4(bl[t2], sb + 3*TILE_B + b_lane + t2*16*80 + kk*32);
            }
#pragma unroll
            for (int im = 0; im < 2; im++)
#pragma unroll
                for (int j = 0; j < 8; j++){
                    const uint32_t b0 = bh[j>>1][(j&1)*2];
                    const uint32_t b1 = bh[j>>1][(j&1)*2+1];
                    mma16816(acc[im][j], ah[im], b0, b1);
                    mma16816(acc[im][j], al[im], b0, b1);
                    mma16816(acc[im][j], ah[im],
                             bl[j>>1][(j&1)*2], bl[j>>1][(j&1)*2+1]);
                }
        }

        if (s+1 < NKT) STS_STAGE(s+1);
        __syncthreads();
    }
#undef LDG_STAGE
#undef STS_STAGE

    // ---------------- epilogue: regs -> (RoPE/bias) -> smem -> coalesced GMEM
    float* Ds = (float*)sm;            // 128 x 132 staging
#pragma unroll
    for (int im = 0; im < 2; im++){
#pragma unroll
        for (int j = 0; j < 8; j++){
            const int cl = wn*64 + j*8 + (lane&3)*2;   // even local col
#pragma unroll
            for (int rr = 0; rr < 2; rr++){
                const int r = wm*32 + im*16 + (lane>>2) + rr*8;
                float v1 = acc[im][j][rr*2+0];
                float v2 = acc[im][j][rr*2+1];
                const int m = m0 + r;
                if (m < Mn){
                    const int gc = n0 + cl;
                    if (EPI == 0){
                        const int bb = m / Nn;
                        const int n  = m - bb*Nn;
                        const int sec = gc / Cn;
                        const int d   = gc & 63;
                        if (sec < 2 && n > 0){
                            const float cs = cosb[(n-1)*(Dn/2) + (d>>1)];
                            const float sn = sinb[(n-1)*(Dn/2) + (d>>1)];
                            const float r1 = v1*cs - v2*sn;
                            const float r2 = v1*sn + v2*cs;
                            v1 = r1; v2 = r2;
                        }
                        if (sec == 0){ v1 *= 0.125f; v2 *= 0.125f; }
                    } else {
                        v1 += bias[gc]; v2 += bias[gc+1];
                    }
                }
                Ds[r*132 + cl]   = v1;
                Ds[r*132 + cl+1] = v2;
            }
        }
    }
    __syncthreads();
    {
        const int m = m0 + row;
        if (m < Mn){
            float* dst = ((EPI==0) ? (g_qkv + (size_t)m*QKV_N) : (Out + (size_t)m*Cn))
                         + n0 + half*64;
            const float* src = &Ds[row*132 + half*64];
#pragma unroll
            for (int j = 0; j < 64; j += 4)
                *(float4*)&dst[j] = *(const float4*)&src[j];
        }
    }
}

// ---------------------------------------------------------------------------
// Flash attention (SIMT fp32; reads strided g_qkv rows)
// ---------------------------------------------------------------------------
__global__ __launch_bounds__(256) void attn_kernel()
{
    __shared__ __align__(16) float Qs[64*64];
    __shared__ __align__(16) float KT2[64*64];   // K^T during S, then P
    __shared__ __align__(16) float Vs[64*64];

    const int qt  = blockIdx.x;
    const int bh  = blockIdx.y;
    const int bb  = bh / Hn;
    const int h   = bh - bb*Hn;
    const int tid = threadIdx.x;
    const int ty  = tid >> 4;
    const int tx  = tid & 15;
    const int lr  = tid >> 2;
    const int lc  = (tid & 3) << 4;

    const size_t base = (size_t)bb*Nn*QKV_N + h*Dn;
    const float* Qg = g_qkv + base;
    const float* Kg = g_qkv + base + Cn;
    const float* Vg = g_qkv + base + 2*Cn;

    {
        const int r = qt*64 + lr;
#pragma unroll
        for (int q = 0; q < 16; q += 4) {
            float4 v = (r < Nn) ? *(const float4*)(Qg + (size_t)r*QKV_N + lc + q)
                                : make_float4(0.f,0.f,0.f,0.f);
            Qs[lr*64 + lc+q+0] = v.x; Qs[lr*64 + lc+q+1] = v.y;
            Qs[lr*64 + lc+q+2] = v.z; Qs[lr*64 + lc+q+3] = v.w;
        }
    }

    float m_i[4], l_i[4], O[4][4];
#pragma unroll
    for (int i = 0; i < 4; i++) {
        m_i[i] = -1e30f; l_i[i] = 0.f;
#pragma unroll
        for (int j = 0; j < 4; j++) O[i][j] = 0.f;
    }

    const int NT = (Nn + 63) / 64;
    for (int t = 0; t < NT; t++) {
        __syncthreads();
        {
            const int r = t*64 + lr;
            const bool ok = (r < Nn);
#pragma unroll
            for (int q = 0; q < 16; q += 4) {
                float4 kv = ok ? *(const float4*)(Kg + (size_t)r*QKV_N + lc + q)
                               : make_float4(0.f,0.f,0.f,0.f);
                KT2[(lc+q+0)*64 + lr] = kv.x;
                KT2[(lc+q+1)*64 + lr] = kv.y;
                KT2[(lc+q+2)*64 + lr] = kv.z;
                KT2[(lc+q+3)*64 + lr] = kv.w;
                float4 vv = ok ? *(const float4*)(Vg + (size_t)r*QKV_N + lc + q)
                               : make_float4(0.f,0.f,0.f,0.f);
                Vs[lr*64 + lc+q+0] = vv.x; Vs[lr*64 + lc+q+1] = vv.y;
                Vs[lr*64 + lc+q+2] = vv.z; Vs[lr*64 + lc+q+3] = vv.w;
            }
        }
        __syncthreads();

        float s[4][4];
#pragma unroll
        for (int i = 0; i < 4; i++)
#pragma unroll
            for (int j = 0; j < 4; j++) s[i][j] = 0.f;

#pragma unroll 4
        for (int d4 = 0; d4 < 64; d4 += 4) {
            float4 q4[4];
#pragma unroll
            for (int i = 0; i < 4; i++)
                q4[i] = *(const float4*)&Qs[(ty*4+i)*64 + d4];
#pragma unroll
            for (int u = 0; u < 4; u++) {
                float4 k4 = *(const float4*)&KT2[(d4+u)*64 + tx*4];
                const float kf[4] = {k4.x,k4.y,k4.z,k4.w};
#pragma unroll
                for (int i = 0; i < 4; i++) {
                    const float qf = (u==0)?q4[i].x:(u==1)?q4[i].y:(u==2)?q4[i].z:q4[i].w;
#pragma unroll
                    for (int j = 0; j < 4; j++) s[i][j] += qf * kf[j];
                }
            }
        }

        const int kb = t*64 + tx*4;
#pragma unroll
        for (int j = 0; j < 4; j++)
            if (kb + j >= Nn) {
#pragma unroll
                for (int i = 0; i < 4; i++) s[i][j] = -1e30f;
            }

        __syncthreads();

#pragma unroll
        for (int i = 0; i < 4; i++) {
            float mx = fmaxf(fmaxf(s[i][0],s[i][1]), fmaxf(s[i][2],s[i][3]));
#pragma unroll
            for (int off = 8; off > 0; off >>= 1)
                mx = fmaxf(mx, __shfl_xor_sync(0xffffffffu, mx, off, 16));
            const float mnew  = fmaxf(m_i[i], mx);
            const float alpha = __expf(m_i[i] - mnew);
            const float p0 = __expf(s[i][0]-mnew), p1 = __expf(s[i][1]-mnew);
            const float p2 = __expf(s[i][2]-mnew), p3 = __expf(s[i][3]-mnew);
            float rs = p0+p1+p2+p3;
#pragma unroll
            for (int off = 8; off > 0; off >>= 1)
                rs += __shfl_xor_sync(0xffffffffu, rs, off, 16);
            l_i[i] = l_i[i]*alpha + rs;
            m_i[i] = mnew;
#pragma unroll
            for (int j = 0; j < 4; j++) O[i][j] *= alpha;
            *(float4*)&KT2[(ty*4+i)*64 + tx*4] = make_float4(p0,p1,p2,p3);
        }
        __syncthreads();

#pragma unroll 4
        for (int k4 = 0; k4 < 64; k4 += 4) {
            float4 p4[4];
#pragma unroll
            for (int i = 0; i < 4; i++)
                p4[i] = *(const float4*)&KT2[(ty*4+i)*64 + k4];
#pragma unroll
            for (int u = 0; u < 4; u++) {
                float4 v4 = *(const float4*)&Vs[(k4+u)*64 + tx*4];
                const float vf[4] = {v4.x,v4.y,v4.z,v4.w};
#pragma unroll
                for (int i = 0; i < 4; i++) {
                    const float pf = (u==0)?p4[i].x:(u==1)?p4[i].y:(u==2)?p4[i].z:p4[i].w;
#pragma unroll
                    for (int j = 0; j < 4; j++) O[i][j] += pf * vf[j];
                }
            }
        }
    }

#pragma unroll
    for (int i = 0; i < 4; i++) {
        const int qr = qt*64 + ty*4 + i;
        if (qr < Nn) {
            const float inv = 1.0f / l_i[i];
            float4 o4 = make_float4(O[i][0]*inv, O[i][1]*inv, O[i][2]*inv, O[i][3]*inv);
            *(float4*)&g_ao[((size_t)bb*Nn + qr)*Cn + h*Dn + tx*4] = o4;
        }
    }
}

// ---------------------------------------------------------------------------
extern "C" void kernel_launch(void* const* d_in, const int* in_sizes, int n_in,
                              void* d_out, int out_size)
{
    (void)in_sizes; (void)n_in; (void)out_size;
    const float* x      = (const float*)d_in[0];
    const float* w_qkv  = (const float*)d_in[1];
    const float* w_proj = (const float*)d_in[2];
    const float* b_proj = (const float*)d_in[3];
    const float* cosb   = (const float*)d_in[4];
    const float* sinb   = (const float*)d_in[5];
    float* out = (float*)d_out;

    cudaFuncSetAttribute(gemm_tc<0>, cudaFuncAttributeMaxDynamicSharedMemorySize, SMEM_DYN);
    cudaFuncSetAttribute(gemm_tc<1>, cudaFuncAttributeMaxDynamicSharedMemorySize, SMEM_DYN);

    const int MT = (Mn + 127) / 128;   // 145
    gemm_tc<0><<<dim3(QKV_N/128, MT), 256, SMEM_DYN>>>(x, w_qkv, cosb, sinb, nullptr, nullptr);
    attn_kernel<<<dim3((Nn+63)/64, Bn*Hn), 256>>>();
    gemm_tc<1><<<dim3(Cn/128, MT), 256, SMEM_DYN>>>(nullptr, w_proj, nullptr, nullptr, b_proj, out);
}

// round 4
// speedup vs baseline: 2.1758x; 1.5490x over previous
#include <cuda_runtime.h>
#include <cuda_bf16.h>
#include <cstdint>

#define Bn 32
#define Nn 577
#define Cn 768
#define Hn 12
#define Dn 64
#define Mn (Bn*Nn)          // 18464
#define QKV_N (3*Cn)        // 2304
#define BHD ((size_t)Bn*Hn*Nn*Dn)   // 14,180,352

// Scratch (__device__ globals: allocation-free rule) — all bf16 hi/lo pairs
__device__ __align__(16) __nv_bfloat16 g_qh[BHD], g_ql[BHD];
__device__ __align__(16) __nv_bfloat16 g_kh[BHD], g_kl[BHD];
__device__ __align__(16) __nv_bfloat16 g_vh[BHD], g_vl[BHD];
__device__ __align__(16) __nv_bfloat16 g_aoh[(size_t)Mn*Cn], g_aol[(size_t)Mn*Cn];

// ---------------------------------------------------------------------------
// helpers
// ---------------------------------------------------------------------------
__device__ __forceinline__ uint32_t smem_u32(const void* p){
    uint32_t a;
    asm("{ .reg .u64 t; cvta.to.shared.u64 t, %1; cvt.u32.u64 %0, t; }"
        : "=r"(a) : "l"(p));
    return a;
}
__device__ __forceinline__ void ldsm4(uint32_t (&r)[4], uint32_t a){
    asm volatile("ldmatrix.sync.aligned.m8n8.x4.shared.b16 {%0,%1,%2,%3}, [%4];"
        : "=r"(r[0]),"=r"(r[1]),"=r"(r[2]),"=r"(r[3]) : "r"(a));
}
__device__ __forceinline__ void ldsm4t(uint32_t (&r)[4], uint32_t a){
    asm volatile("ldmatrix.sync.aligned.m8n8.x4.trans.shared.b16 {%0,%1,%2,%3}, [%4];"
        : "=r"(r[0]),"=r"(r[1]),"=r"(r[2]),"=r"(r[3]) : "r"(a));
}
__device__ __forceinline__ void mma16816(float* c, const uint32_t* a,
                                         uint32_t b0, uint32_t b1){
    asm volatile("mma.sync.aligned.m16n8k16.row.col.f32.bf16.bf16.f32 "
        "{%0,%1,%2,%3}, {%4,%5,%6,%7}, {%8,%9}, {%0,%1,%2,%3};"
        : "+f"(c[0]),"+f"(c[1]),"+f"(c[2]),"+f"(c[3])
        : "r"(a[0]),"r"(a[1]),"r"(a[2]),"r"(a[3]), "r"(b0),"r"(b1));
}
__device__ __forceinline__ uint32_t packbf(float x, float y){
    __nv_bfloat162 t = __floats2bfloat162_rn(x, y);
    return *reinterpret_cast<uint32_t*>(&t);
}
// 8 fp32 -> 4 b32 hi-bf16 pairs + 4 b32 lo-bf16 pairs (hi + lo ≈ fp32)
__device__ __forceinline__ void cvt8_split(float4 a, float4 b, uint32_t* h, uint32_t* l){
    float f[8] = {a.x,a.y,a.z,a.w,b.x,b.y,b.z,b.w};
    float hf[8];
#pragma unroll
    for (int i=0;i<8;i++) hf[i] = __bfloat162float(__float2bfloat16(f[i]));
#pragma unroll
    for (int i=0;i<4;i++){
        h[i] = packbf(f[2*i], f[2*i+1]);
        l[i] = packbf(f[2*i]-hf[2*i], f[2*i+1]-hf[2*i+1]);
    }
}
__device__ __forceinline__ void store_pair(__nv_bfloat16* dh, __nv_bfloat16* dl,
                                           size_t idx, float v1, float v2){
    const __nv_bfloat16 h1 = __float2bfloat16(v1), h2 = __float2bfloat16(v2);
    uint32_t hp; { __nv_bfloat162 t; t.x=h1; t.y=h2; hp=*reinterpret_cast<uint32_t*>(&t); }
    *reinterpret_cast<uint32_t*>(dh + idx) = hp;
    *reinterpret_cast<uint32_t*>(dl + idx) =
        packbf(v1 - __bfloat162float(h1), v2 - __bfloat162float(h2));
}

// ---------------------------------------------------------------------------
// HMMA bf16x3 GEMM: D[128x128] = A[M,768] @ B[N,768]^T (fp32 accum)
// EPI==0: A = x (fp32, split in-kernel); epilogue RoPE+scale -> bf16 q/k/v
// EPI==1: A = g_aoh/g_aol (bf16 direct); epilogue +bias -> fp32 Out
// ---------------------------------------------------------------------------
#define KT 32
#define NKT (Cn/KT)          // 24
#define TILE_B 10240
#define STAGE_B 40960
#define SMEM_DYN (2*STAGE_B)

template<int EPI>
__global__ __launch_bounds__(256) void gemm_tc(
    const float* __restrict__ Ain, const float* __restrict__ Bw,
    const float* __restrict__ cosb, const float* __restrict__ sinb,
    const float* __restrict__ bias, float* __restrict__ Out)
{
    extern __shared__ char sm[];

    const int tid  = threadIdx.x;
    const int wid  = tid >> 5;
    const int lane = tid & 31;
    const int m0 = blockIdx.y * 128;
    const int n0 = blockIdx.x * 128;

    const int row  = tid >> 1;          // 0..127
    const int half = tid & 1;           // 0..1
    const bool mok = (m0 + row) < Mn;
    const float* pa = Ain + (size_t)(m0+row)*Cn + half*16;
    const __nv_bfloat16* pah = g_aoh + (size_t)(m0+row)*Cn + half*16;
    const __nv_bfloat16* pal = g_aol + (size_t)(m0+row)*Cn + half*16;
    const float* pb = Bw + (size_t)(n0+row)*Cn + half*16;
    const uint32_t sts_off = (uint32_t)row*80 + (uint32_t)half*32;

    const uint32_t smb = smem_u32(sm);

    const int wm = wid & 3;
    const int wn = wid >> 2;
    const uint32_t a_lane = (uint32_t)((wm*32 + (lane&15))*80 + (lane>>4)*16);
    const uint32_t b_lane = (uint32_t)((wn*64 + (lane&7) + ((lane>>4)<<3))*80
                                       + ((lane>>3)&1)*16);

    float acc[2][8][4];
#pragma unroll
    for (int im=0;im<2;im++)
#pragma unroll
        for (int j=0;j<8;j++)
#pragma unroll
            for (int q=0;q<4;q++) acc[im][j][q] = 0.f;

    float4 a4[4], b4[4];
    uint4 abh[2], abl[2];

#define LDG_STAGE(s_) do{ \
    const float* qb = pb + (s_)*KT; \
    if (EPI==0){ \
        const float* qa = pa + (s_)*KT; \
        if (mok){ a4[0]=*(const float4*)qa;     a4[1]=*(const float4*)(qa+4); \
                  a4[2]=*(const float4*)(qa+8); a4[3]=*(const float4*)(qa+12);} \
        else { a4[0]=a4[1]=a4[2]=a4[3]=make_float4(0.f,0.f,0.f,0.f); } \
    } else { \
        if (mok){ abh[0]=*(const uint4*)(pah + (s_)*KT); abh[1]=*(const uint4*)(pah + (s_)*KT + 8); \
                  abl[0]=*(const uint4*)(pal + (s_)*KT); abl[1]=*(const uint4*)(pal + (s_)*KT + 8);} \
        else { abh[0]=abh[1]=abl[0]=abl[1]=make_uint4(0,0,0,0); } \
    } \
    b4[0]=*(const float4*)qb;     b4[1]=*(const float4*)(qb+4); \
    b4[2]=*(const float4*)(qb+8); b4[3]=*(const float4*)(qb+12); }while(0)

#define STS_STAGE(s_) do{ \
    char* sp = sm + (size_t)((s_)&1)*STAGE_B; \
    uint32_t h[4], l[4]; \
    if (EPI==0){ \
        cvt8_split(a4[0],a4[1],h,l); \
        *(uint4*)(sp + sts_off)              = make_uint4(h[0],h[1],h[2],h[3]); \
        *(uint4*)(sp + TILE_B + sts_off)     = make_uint4(l[0],l[1],l[2],l[3]); \
        cvt8_split(a4[2],a4[3],h,l); \
        *(uint4*)(sp + sts_off + 16)         = make_uint4(h[0],h[1],h[2],h[3]); \
        *(uint4*)(sp + TILE_B + sts_off + 16)= make_uint4(l[0],l[1],l[2],l[3]); \
    } else { \
        *(uint4*)(sp + sts_off)              = abh[0]; \
        *(uint4*)(sp + sts_off + 16)         = abh[1]; \
        *(uint4*)(sp + TILE_B + sts_off)     = abl[0]; \
        *(uint4*)(sp + TILE_B + sts_off + 16)= abl[1]; \
    } \
    cvt8_split(b4[0],b4[1],h,l); \
    *(uint4*)(sp + 2*TILE_B + sts_off)   = make_uint4(h[0],h[1],h[2],h[3]); \
    *(uint4*)(sp + 3*TILE_B + sts_off)   = make_uint4(l[0],l[1],l[2],l[3]); \
    cvt8_split(b4[2],b4[3],h,l); \
    *(uint4*)(sp + 2*TILE_B + sts_off+16)= make_uint4(h[0],h[1],h[2],h[3]); \
    *(uint4*)(sp + 3*TILE_B + sts_off+16)= make_uint4(l[0],l[1],l[2],l[3]); }while(0)

    LDG_STAGE(0);
    STS_STAGE(0);
    __syncthreads();

    for (int s = 0; s < NKT; s++){
        if (s+1 < NKT) LDG_STAGE(s+1);

        const uint32_t sb = smb + (uint32_t)(s&1)*STAGE_B;
#pragma unroll
        for (int kk = 0; kk < 2; kk++){
            uint32_t ah[2][4], al[2][4];
            ldsm4(ah[0], sb + a_lane + kk*32);
            ldsm4(ah[1], sb + a_lane + 16*80 + kk*32);
            ldsm4(al[0], sb + TILE_B + a_lane + kk*32);
            ldsm4(al[1], sb + TILE_B + a_lane + 16*80 + kk*32);
            uint32_t bh[4][4], bl[4][4];
#pragma unroll
            for (int t2 = 0; t2 < 4; t2++){
                ldsm4(bh[t2], sb + 2*TILE_B + b_lane + t2*16*80 + kk*32);
                ldsm4(bl[t2], sb + 3*TILE_B + b_lane + t2*16*80 + kk*32);
            }
#pragma unroll
            for (int im = 0; im < 2; im++)
#pragma unroll
                for (int j = 0; j < 8; j++){
                    const uint32_t b0 = bh[j>>1][(j&1)*2];
                    const uint32_t b1 = bh[j>>1][(j&1)*2+1];
                    mma16816(acc[im][j], ah[im], b0, b1);
                    mma16816(acc[im][j], al[im], b0, b1);
                    mma16816(acc[im][j], ah[im],
                             bl[j>>1][(j&1)*2], bl[j>>1][(j&1)*2+1]);
                }
        }

        if (s+1 < NKT) STS_STAGE(s+1);
        __syncthreads();
    }
#undef LDG_STAGE
#undef STS_STAGE

    // ---------------- epilogue
    if (EPI == 0){
        // RoPE + q-scale, write bf16 hi/lo q/k/v in [B,H,N,D]
#pragma unroll
        for (int im = 0; im < 2; im++){
#pragma unroll
            for (int j = 0; j < 8; j++){
                const int cl = wn*64 + j*8 + (lane&3)*2;
#pragma unroll
                for (int rr = 0; rr < 2; rr++){
                    const int r = wm*32 + im*16 + (lane>>2) + rr*8;
                    const int m = m0 + r;
                    if (m >= Mn) continue;
                    float v1 = acc[im][j][rr*2+0];
                    float v2 = acc[im][j][rr*2+1];
                    const int gc  = n0 + cl;
                    const int sec = gc / Cn;
                    const int rem = gc - sec*Cn;
                    const int hh  = rem >> 6;
                    const int d   = rem & 63;
                    const int bb  = m / Nn;
                    const int n   = m - bb*Nn;
                    if (sec < 2 && n > 0){
                        const float cs = cosb[(n-1)*(Dn/2) + (d>>1)];
                        const float sn = sinb[(n-1)*(Dn/2) + (d>>1)];
                        const float r1 = v1*cs - v2*sn;
                        const float r2 = v1*sn + v2*cs;
                        v1 = r1; v2 = r2;
                    }
                    if (sec == 0){ v1 *= 0.125f; v2 *= 0.125f; }
                    const size_t idx = ((size_t)(bb*Hn + hh)*Nn + n)*Dn + d;
                    if (sec == 0)      store_pair(g_qh, g_ql, idx, v1, v2);
                    else if (sec == 1) store_pair(g_kh, g_kl, idx, v1, v2);
                    else               store_pair(g_vh, g_vl, idx, v1, v2);
                }
            }
        }
    } else {
        float* Ds = (float*)sm;            // 128 x 132 staging
#pragma unroll
        for (int im = 0; im < 2; im++){
#pragma unroll
            for (int j = 0; j < 8; j++){
                const int cl = wn*64 + j*8 + (lane&3)*2;
#pragma unroll
                for (int rr = 0; rr < 2; rr++){
                    const int r = wm*32 + im*16 + (lane>>2) + rr*8;
                    float v1 = acc[im][j][rr*2+0];
                    float v2 = acc[im][j][rr*2+1];
                    const int gc = n0 + cl;
                    v1 += bias[gc]; v2 += bias[gc+1];
                    Ds[r*132 + cl]   = v1;
                    Ds[r*132 + cl+1] = v2;
                }
            }
        }
        __syncthreads();
        const int m = m0 + row;
        if (m < Mn){
            float* dst = Out + (size_t)m*Cn + n0 + half*64;
            const float* src = &Ds[row*132 + half*64];
#pragma unroll
            for (int j = 0; j < 64; j += 4)
                *(float4*)&dst[j] = *(const float4*)&src[j];
        }
    }
}

// ---------------------------------------------------------------------------
// HMMA flash attention: CTA = 128 q-rows x (b,h). 8 warps x m16.
// Smem: K/V hi/lo tiles 64x64 bf16, pitch 144B, double buffered.
// ---------------------------------------------------------------------------
#define AT_PITCH 144
#define AT_TILE  (64*AT_PITCH)       // 9216
#define AT_STAGE (4*AT_TILE)         // 36864
#define AT_SMEM  (2*AT_STAGE)        // 73728
#define NTkv ((Nn+63)/64)            // 10

__global__ __launch_bounds__(256) void attn_tc()
{
    extern __shared__ char sm[];
    const uint32_t smb = smem_u32(sm);
    const int tid  = threadIdx.x;
    const int wid  = tid >> 5;
    const int lane = tid & 31;
    const int qt   = blockIdx.x;          // 0..4
    const int bh   = blockIdx.y;          // 0..383
    const int bb   = bh / Hn;
    const int h    = bh - bb*Hn;

    const __nv_bfloat16* Qh = g_qh + (size_t)bh*Nn*Dn;
    const __nv_bfloat16* Ql = g_ql + (size_t)bh*Nn*Dn;
    const __nv_bfloat16* Kh = g_kh + (size_t)bh*Nn*Dn;
    const __nv_bfloat16* Kl = g_kl + (size_t)bh*Nn*Dn;
    const __nv_bfloat16* Vh = g_vh + (size_t)bh*Nn*Dn;
    const __nv_bfloat16* Vl = g_vl + (size_t)bh*Nn*Dn;

    // ---- stage Q (128 rows x 64) hi at 0, lo at 18432; then ldsm to frags
    {
#pragma unroll
        for (int i = 0; i < 4; i++){
            const int idx = tid + i*256;      // 0..1023
            const int r   = idx >> 3;
            const int j   = idx & 7;
            const int gr  = qt*128 + r;
            uint4 vh = make_uint4(0,0,0,0), vl = vh;
            if (gr < Nn){
                vh = *(const uint4*)(Qh + (size_t)gr*Dn + j*8);
                vl = *(const uint4*)(Ql + (size_t)gr*Dn + j*8);
            }
            *(uint4*)(sm + r*AT_PITCH + j*16)         = vh;
            *(uint4*)(sm + 18432 + r*AT_PITCH + j*16) = vl;
        }
    }
    __syncthreads();
    uint32_t qfh[4][4], qfl[4][4];
    {
        const uint32_t qa = smb + (uint32_t)((wid*16 + (lane&15))*AT_PITCH + (lane>>4)*16);
#pragma unroll
        for (int kk = 0; kk < 4; kk++){
            ldsm4(qfh[kk], qa + kk*32);
            ldsm4(qfl[kk], qa + 18432 + kk*32);
        }
    }
    __syncthreads();

#define LOADKV(t_, buf_) do{ \
    const int kv0 = (t_)*64; \
    char* bp = sm + (size_t)(buf_)*AT_STAGE; \
    _Pragma("unroll") \
    for (int i_ = 0; i_ < 8; i_++){ \
        const int idx = tid + i_*256;            /* 0..2047 */ \
        const int ts  = idx >> 9;                /* 0..3 */ \
        const int rem = idx & 511; \
        const int r_  = rem >> 3; \
        const int j_  = rem & 7; \
        const int gr  = kv0 + r_; \
        const __nv_bfloat16* src = (ts==0)?Kh:(ts==1)?Kl:(ts==2)?Vh:Vl; \
        uint4 v = make_uint4(0,0,0,0); \
        if (gr < Nn) v = *(const uint4*)(src + (size_t)gr*Dn + j_*8); \
        *(uint4*)(bp + ts*AT_TILE + r_*AT_PITCH + j_*16) = v; \
    } }while(0)

    LOADKV(0, 0);
    __syncthreads();

    float m0r = -1e30f, m1r = -1e30f, l0r = 0.f, l1r = 0.f;
    float o[8][4];
#pragma unroll
    for (int j=0;j<8;j++)
#pragma unroll
        for (int q=0;q<4;q++) o[j][q] = 0.f;

    for (int t = 0; t < NTkv; t++){
        if (t+1 < NTkv) LOADKV(t+1, (t+1)&1);

        const uint32_t sb = smb + (uint32_t)(t&1)*AT_STAGE;

        // ---- S = Q K^T (3 terms)
        float s[8][4];
#pragma unroll
        for (int j=0;j<8;j++)
#pragma unroll
            for (int q=0;q<4;q++) s[j][q] = 0.f;

#pragma unroll
        for (int kk = 0; kk < 4; kk++){
            uint32_t kh[4][4], kl[4][4];
#pragma unroll
            for (int g = 0; g < 4; g++){
                const uint32_t ka = sb
                    + (uint32_t)((g*16 + (lane&7) + ((lane>>4)<<3))*AT_PITCH
                                 + ((lane>>3)&1)*16 + kk*32);
                ldsm4(kh[g], ka);
                ldsm4(kl[g], ka + AT_TILE);
            }
#pragma unroll
            for (int j = 0; j < 8; j++){
                const int g = j>>1, p = (j&1)*2;
                mma16816(s[j], qfh[kk], kh[g][p], kh[g][p+1]);
                mma16816(s[j], qfl[kk], kh[g][p], kh[g][p+1]);
                mma16816(s[j], qfh[kk], kl[g][p], kl[g][p+1]);
            }
        }

        // ---- mask + online softmax (rows: lane>>2 and +8)
        if (t == NTkv-1){
#pragma unroll
            for (int j = 0; j < 8; j++){
                const int c0 = t*64 + j*8 + (lane&3)*2;
                if (c0   >= Nn){ s[j][0] = -1e30f; s[j][2] = -1e30f; }
                if (c0+1 >= Nn){ s[j][1] = -1e30f; s[j][3] = -1e30f; }
            }
        }
        float mx0 = -1e30f, mx1 = -1e30f;
#pragma unroll
        for (int j = 0; j < 8; j++){
            mx0 = fmaxf(mx0, fmaxf(s[j][0], s[j][1]));
            mx1 = fmaxf(mx1, fmaxf(s[j][2], s[j][3]));
        }
        mx0 = fmaxf(mx0, __shfl_xor_sync(0xffffffffu, mx0, 1));
        mx0 = fmaxf(mx0, __shfl_xor_sync(0xffffffffu, mx0, 2));
        mx1 = fmaxf(mx1, __shfl_xor_sync(0xffffffffu, mx1, 1));
        mx1 = fmaxf(mx1, __shfl_xor_sync(0xffffffffu, mx1, 2));
        const float mn0 = fmaxf(m0r, mx0), mn1 = fmaxf(m1r, mx1);
        const float al0 = __expf(m0r - mn0), al1 = __expf(m1r - mn1);
        float rs0 = 0.f, rs1 = 0.f;
#pragma unroll
        for (int j = 0; j < 8; j++){
            s[j][0] = __expf(s[j][0]-mn0); s[j][1] = __expf(s[j][1]-mn0);
            s[j][2] = __expf(s[j][2]-mn1); s[j][3] = __expf(s[j][3]-mn1);
            rs0 += s[j][0] + s[j][1];
            rs1 += s[j][2] + s[j][3];
        }
        rs0 += __shfl_xor_sync(0xffffffffu, rs0, 1);
        rs0 += __shfl_xor_sync(0xffffffffu, rs0, 2);
        rs1 += __shfl_xor_sync(0xffffffffu, rs1, 1);
        rs1 += __shfl_xor_sync(0xffffffffu, rs1, 2);
        l0r = l0r*al0 + rs0;  m0r = mn0;
        l1r = l1r*al1 + rs1;  m1r = mn1;
#pragma unroll
        for (int j = 0; j < 8; j++){
            o[j][0] *= al0; o[j][1] *= al0;
            o[j][2] *= al1; o[j][3] *= al1;
        }

        // ---- O += P V (3 terms), P repacked in registers
#pragma unroll
        for (int kk = 0; kk < 4; kk++){
            uint32_t pha[4], pla[4];
            {
                const int j0 = 2*kk, j1 = 2*kk+1;
                float h0, h1;
                h0 = __bfloat162float(__float2bfloat16(s[j0][0]));
                h1 = __bfloat162float(__float2bfloat16(s[j0][1]));
                pha[0] = packbf(s[j0][0], s[j0][1]);
                pla[0] = packbf(s[j0][0]-h0, s[j0][1]-h1);
                h0 = __bfloat162float(__float2bfloat16(s[j0][2]));
                h1 = __bfloat162float(__float2bfloat16(s[j0][3]));
                pha[1] = packbf(s[j0][2], s[j0][3]);
                pla[1] = packbf(s[j0][2]-h0, s[j0][3]-h1);
                h0 = __bfloat162float(__float2bfloat16(s[j1][0]));
                h1 = __bfloat162float(__float2bfloat16(s[j1][1]));
                pha[2] = packbf(s[j1][0], s[j1][1]);
                pla[2] = packbf(s[j1][0]-h0, s[j1][1]-h1);
                h0 = __bfloat162float(__float2bfloat16(s[j1][2]));
                h1 = __bfloat162float(__float2bfloat16(s[j1][3]));
                pha[3] = packbf(s[j1][2], s[j1][3]);
                pla[3] = packbf(s[j1][2]-h0, s[j1][3]-h1);
            }
            uint32_t vh[4][4], vl[4][4];
#pragma unroll
            for (int g = 0; g < 4; g++){
                const uint32_t va = sb + 2*AT_TILE
                    + (uint32_t)((kk*16 + (lane&7) + ((lane>>3)&1)*8)*AT_PITCH
                                 + ((lane>>4)*8 + g*16)*2);
                ldsm4t(vh[g], va);
                ldsm4t(vl[g], va + AT_TILE);
            }
#pragma unroll
            for (int j = 0; j < 8; j++){
                const int g = j>>1, p = (j&1)*2;
                mma16816(o[j], pha, vh[g][p], vh[g][p+1]);
                mma16816(o[j], pla, vh[g][p], vh[g][p+1]);
                mma16816(o[j], pha, vl[g][p], vl[g][p+1]);
            }
        }
        __syncthreads();
    }
#undef LOADKV

    // ---- normalize + store AO bf16 hi/lo ([B*N, C] at col h*64+d)
    const float inv0 = 1.f / l0r, inv1 = 1.f / l1r;
    const int r0 = qt*128 + wid*16 + (lane>>2);
    const int r1 = r0 + 8;
#pragma unroll
    for (int j = 0; j < 8; j++){
        const int col = h*Dn + j*8 + (lane&3)*2;
        if (r0 < Nn)
            store_pair(g_aoh, g_aol, (size_t)(bb*Nn + r0)*Cn + col,
                       o[j][0]*inv0, o[j][1]*inv0);
        if (r1 < Nn)
            store_pair(g_aoh, g_aol, (size_t)(bb*Nn + r1)*Cn + col,
                       o[j][2]*inv1, o[j][3]*inv1);
    }
}

// ---------------------------------------------------------------------------
extern "C" void kernel_launch(void* const* d_in, const int* in_sizes, int n_in,
                              void* d_out, int out_size)
{
    (void)in_sizes; (void)n_in; (void)out_size;
    const float* x      = (const float*)d_in[0];
    const float* w_qkv  = (const float*)d_in[1];
    const float* w_proj = (const float*)d_in[2];
    const float* b_proj = (const float*)d_in[3];
    const float* cosb   = (const float*)d_in[4];
    const float* sinb   = (const float*)d_in[5];
    float* out = (float*)d_out;

    cudaFuncSetAttribute(gemm_tc<0>, cudaFuncAttributeMaxDynamicSharedMemorySize, SMEM_DYN);
    cudaFuncSetAttribute(gemm_tc<1>, cudaFuncAttributeMaxDynamicSharedMemorySize, SMEM_DYN);
    cudaFuncSetAttribute(attn_tc,    cudaFuncAttributeMaxDynamicSharedMemorySize, AT_SMEM);

    const int MT = (Mn + 127) / 128;   // 145
    gemm_tc<0><<<dim3(QKV_N/128, MT), 256, SMEM_DYN>>>(x, w_qkv, cosb, sinb, nullptr, nullptr);
    attn_tc<<<dim3((Nn+127)/128, Bn*Hn), 256, AT_SMEM>>>();
    gemm_tc<1><<<dim3(Cn/128, MT), 256, SMEM_DYN>>>(nullptr, w_proj, nullptr, nullptr, b_proj, out);
}